// round 1
// baseline (speedup 1.0000x reference)
#include <cuda_runtime.h>

typedef unsigned long long u64;

#define N_FEAT 256
#define OUTD   64
#define NPB    256          // nodes per block
#define KC     32           // k chunk
#define XS_STRIDE 33        // conflict-free transpose stride
#define HS_STRIDE 66
#define WS_FLOATS (N_FEAT * OUTD)        // 16384
#define XS_FLOATS (NPB * XS_STRIDE)      // 8448
#define FC_OFF    (WS_FLOATS + XS_FLOATS) // 24832
#define SMEM_FLOATS (FC_OFF + 1089)       // 25921 floats = 103684 B

__device__ __align__(16) float g_Wc[WS_FLOATS];   // [k][j], j<32: z-gate, j>=32: h-tilde
__device__ __align__(16) float g_bias[OUTD];

// ---------------------------------------------------------------------------
// Prep: fold the two diffusion-direction weights (only x-rows matter, h0 = 0)
// ---------------------------------------------------------------------------
__global__ void prep_kernel(const float* __restrict__ wz, const float* __restrict__ bz,
                            const float* __restrict__ wh, const float* __restrict__ bh) {
    int idx = blockIdx.x * blockDim.x + threadIdx.x;
    if (idx < WS_FLOATS) {
        int k = idx >> 6;          // 0..255  (x feature row)
        int j = idx & 63;          // 0..63
        const int D1 = 288 * 32;   // offset of w[1] in (2,288,32)
        float v;
        if (j < 32) v = wz[k * 32 + j]        + wz[D1 + k * 32 + j];
        else        v = wh[k * 32 + (j - 32)] + wh[D1 + k * 32 + (j - 32)];
        g_Wc[idx] = v;
    }
    if (idx < 32)        g_bias[idx] = bz[idx];
    else if (idx < 64)   g_bias[idx] = bh[idx - 32];
}

// ---------------------------------------------------------------------------
// Packed f32x2 helpers (B300: 3-reg FFMA is half rate; FFMA2 restores full)
// ---------------------------------------------------------------------------
__device__ __forceinline__ u64 bcast2(float v) {
    u64 r; asm("mov.b64 %0, {%1, %1};" : "=l"(r) : "f"(v)); return r;
}
__device__ __forceinline__ void ffma2(u64& d, u64 a, u64 b) {
    asm("fma.rn.f32x2 %0, %1, %2, %0;" : "+l"(d) : "l"(a), "l"(b));
}
__device__ __forceinline__ void unpack2(u64 v, float& lo, float& hi) {
    asm("mov.b64 {%0, %1}, %2;" : "=f"(lo), "=f"(hi) : "l"(v));
}

// ---------------------------------------------------------------------------
// Fused GEMM [NPB,256]x[256,64] + GRU-gate + fc head
// ---------------------------------------------------------------------------
__global__ void __launch_bounds__(256, 2)
fused_kernel(const float* __restrict__ x,
             const float* __restrict__ fc1w, const float* __restrict__ fc1b,
             const float* __restrict__ fc2w, const float* __restrict__ fc2b,
             float* __restrict__ out, int n)
{
    extern __shared__ float smem[];
    float* Ws = smem;                 // [256][64]
    float* Xs = smem + WS_FLOATS;     // [NPB][33]
    float* FC = smem + FC_OFF;        // fc1w(1024) fc1b(32) fc2w(32) fc2b(1)

    const int tid = threadIdx.x;
    const int og  = tid & 3;          // output group: columns j = 2*og + 8*p (+0/1)
    const int ng  = tid >> 2;         // node group: 4 nodes
    const int nodeBase = blockIdx.x * NPB;

    // --- stage weights into smem (read from L2-resident g_Wc) ---
    for (int it = 0; it < WS_FLOATS / 1024; it++) {
        int i = tid * 4 + it * 1024;
        *(float4*)(Ws + i) = *(const float4*)(g_Wc + i);
    }
    for (int i = tid; i < 1024; i += 256) FC[i] = fc1w[i];
    if (tid < 32) { FC[1024 + tid] = fc1b[tid]; FC[1056 + tid] = fc2w[tid]; }
    if (tid == 0) FC[1088] = fc2b[0];

    // --- accumulators: 4 nodes x 8 j-pairs, packed along j, init = bias ---
    u64 acc[4][8];
    #pragma unroll
    for (int p = 0; p < 8; p++) {
        u64 b = *(const u64*)(g_bias + 2 * og + 8 * p);
        acc[0][p] = b; acc[1][p] = b; acc[2][p] = b; acc[3][p] = b;
    }

    for (int kc = 0; kc < N_FEAT; kc += KC) {
        __syncthreads();
        // coalesced gmem load of [NPB x KC] x-chunk, transpose into Xs[node][k]
        #pragma unroll
        for (int q = 0; q < 8; q++) {
            int f  = tid + 256 * q;
            int nl = f >> 3;              // local node 0..255
            int kk = (f & 7) * 4;         // local k 0,4,...,28
            int gn = nodeBase + nl;
            if (gn > n - 1) gn = n - 1;   // clamp tail (stores guarded later)
            float4 v = *(const float4*)(x + (size_t)gn * N_FEAT + kc + kk);
            Xs[nl * XS_STRIDE + kk + 0] = v.x;
            Xs[nl * XS_STRIDE + kk + 1] = v.y;
            Xs[nl * XS_STRIDE + kk + 2] = v.z;
            Xs[nl * XS_STRIDE + kk + 3] = v.w;
        }
        __syncthreads();

        const float* wbase = Ws + kc * OUTD + 2 * og;
        const float* xbase = Xs + (ng * 4) * XS_STRIDE;
        #pragma unroll 8
        for (int k = 0; k < KC; k++) {
            u64 w[8];
            #pragma unroll
            for (int p = 0; p < 8; p++)
                w[p] = *(const u64*)(wbase + k * OUTD + 8 * p);   // LDS.64, conflict-free
            #pragma unroll
            for (int i = 0; i < 4; i++) {
                u64 xb = bcast2(xbase[i * XS_STRIDE + k]);
                #pragma unroll
                for (int p = 0; p < 8; p++)
                    ffma2(acc[i][p], xb, w[p]);                   // FFMA2, full-rate fp32
            }
        }
    }

    // --- dump pre-activations to smem (reuse Ws/Xs region) ---
    __syncthreads();
    float* Hs = smem;   // [NPB][HS_STRIDE]
    #pragma unroll
    for (int i = 0; i < 4; i++) {
        #pragma unroll
        for (int p = 0; p < 8; p++)
            *(u64*)(Hs + (ng * 4 + i) * HS_STRIDE + 2 * og + 8 * p) = acc[i][p];
    }
    __syncthreads();

    // --- epilogue: one node per thread ---
    const float* hr = Hs + tid * HS_STRIDE;
    float h[32];
    #pragma unroll 8
    for (int j = 0; j < 32; j++) {
        float z  = 1.f / (1.f + __expf(-hr[j]));      // update gate
        float ht = tanhf(hr[32 + j]);                 // candidate
        h[j] = (1.f - z) * ht;                        // h = (1-z)*h_tilde  (h0 = 0)
    }
    float hid[32];
    #pragma unroll
    for (int i = 0; i < 32; i++) hid[i] = FC[1024 + i];
    #pragma unroll 4
    for (int j = 0; j < 32; j++) {
        float hj = h[j];
        #pragma unroll
        for (int i4 = 0; i4 < 8; i4++) {
            float4 w4 = *(const float4*)(FC + j * 32 + i4 * 4);   // broadcast LDS.128
            hid[i4 * 4 + 0] = fmaf(hj, w4.x, hid[i4 * 4 + 0]);
            hid[i4 * 4 + 1] = fmaf(hj, w4.y, hid[i4 * 4 + 1]);
            hid[i4 * 4 + 2] = fmaf(hj, w4.z, hid[i4 * 4 + 2]);
            hid[i4 * 4 + 3] = fmaf(hj, w4.w, hid[i4 * 4 + 3]);
        }
    }
    float o = FC[1088];
    #pragma unroll
    for (int i = 0; i < 32; i++)
        o = fmaf(fmaxf(hid[i], 0.f), FC[1056 + i], o);

    int node = nodeBase + tid;
    if (node < n) out[node] = 1.f / (1.f + __expf(-o));
}

// ---------------------------------------------------------------------------
// Launch. Inputs (metadata order): x, edge_index(dead), w_z, b_z, w_r(dead),
// b_r(dead), w_h, b_h, fc1_w, fc1_b, fc2_w, fc2_b. Output: [N,1] float.
// ---------------------------------------------------------------------------
extern "C" void kernel_launch(void* const* d_in, const int* in_sizes, int n_in,
                              void* d_out, int out_size) {
    const float* x    = (const float*)d_in[0];
    const float* wz   = (const float*)d_in[2];
    const float* bz   = (const float*)d_in[3];
    const float* wh   = (const float*)d_in[6];
    const float* bh   = (const float*)d_in[7];
    const float* fc1w = (const float*)d_in[8];
    const float* fc1b = (const float*)d_in[9];
    const float* fc2w = (const float*)d_in[10];
    const float* fc2b = (const float*)d_in[11];
    float* out = (float*)d_out;

    const int n = out_size;   // N nodes, output is [N,1]

    prep_kernel<<<(WS_FLOATS + 255) / 256, 256>>>(wz, bz, wh, bh);

    cudaFuncSetAttribute(fused_kernel, cudaFuncAttributeMaxDynamicSharedMemorySize,
                         SMEM_FLOATS * (int)sizeof(float));
    int nb = (n + NPB - 1) / NPB;
    fused_kernel<<<nb, 256, SMEM_FLOATS * sizeof(float)>>>(
        x, fc1w, fc1b, fc2w, fc2b, out, n);
}

// round 3
// speedup vs baseline: 1.5297x; 1.5297x over previous
#include <cuda_runtime.h>
#include <cuda_bf16.h>

typedef unsigned int u32;
typedef unsigned short u16;

#define NFEAT 256
#define NPB   256
#define NTHR  256

// ---- smem layout (bytes) ----
#define W_STRIDE 528                        // 64 rows x (512B data + 16 pad) -> ldmatrix conflict-free
#define X_STRIDE 48                         // 256 rows x (32B data + 16 pad) -> ldmatrix conflict-free
#define OFF_WHI  0
#define OFF_WLO  (64 * W_STRIDE)            // 33792
#define OFF_XHI  (2 * 64 * W_STRIDE)        // 67584
#define OFF_XLO  (OFF_XHI + 256 * X_STRIDE) // 79872
#define OFF_FC   (OFF_XLO + 256 * X_STRIDE) // 92160
#define FC_FLOATS 1160
#define SMEM_BYTES (OFF_FC + FC_FLOATS * 4) // 96800  -> 2 CTAs/SM

// W (B operand) folded + split: [n=64][k=256] row-major bf16
__device__ __align__(16) u16 g_Whi[64 * 256];
__device__ __align__(16) u16 g_Wlo[64 * 256];

// ---------------------------------------------------------------------------
// Prep: wc[j][k] = (wz[0]+wz[1]) for j<32 else (wh[0]+wh[1]); x-rows only
// (h0 = 0 kills the H part of the concat and the whole r-gate).
// ---------------------------------------------------------------------------
__global__ void prep_kernel(const float* __restrict__ wz, const float* __restrict__ wh) {
    int idx = blockIdx.x * 256 + threadIdx.x;
    if (idx >= 64 * 256) return;
    int j = idx >> 8, k = idx & 255;
    const int D1 = 288 * 32;
    float wc = (j < 32) ? (wz[k * 32 + j] + wz[D1 + k * 32 + j])
                        : (wh[k * 32 + (j - 32)] + wh[D1 + k * 32 + (j - 32)]);
    __nv_bfloat16 h = __float2bfloat16(wc);
    __nv_bfloat16 l = __float2bfloat16(wc - __bfloat162float(h));
    g_Whi[j * 256 + k] = *reinterpret_cast<u16*>(&h);
    g_Wlo[j * 256 + k] = *reinterpret_cast<u16*>(&l);
}

// ---------------------------------------------------------------------------
// helpers
// ---------------------------------------------------------------------------
__device__ __forceinline__ u32 s2u(const void* p) {
    u32 a;
    asm("{ .reg .u64 t; cvta.to.shared.u64 t, %1; cvt.u32.u64 %0, t; }" : "=r"(a) : "l"(p));
    return a;
}
__device__ __forceinline__ void ldsm4(u32 a, u32& r0, u32& r1, u32& r2, u32& r3) {
    asm volatile("ldmatrix.sync.aligned.m8n8.x4.shared.b16 {%0,%1,%2,%3}, [%4];"
                 : "=r"(r0), "=r"(r1), "=r"(r2), "=r"(r3) : "r"(a));
}
__device__ __forceinline__ void mma16816(float* c, u32 a0, u32 a1, u32 a2, u32 a3,
                                         u32 b0, u32 b1) {
    asm volatile("mma.sync.aligned.m16n8k16.row.col.f32.bf16.bf16.f32 "
                 "{%0,%1,%2,%3},{%4,%5,%6,%7},{%8,%9},{%0,%1,%2,%3};"
                 : "+f"(c[0]), "+f"(c[1]), "+f"(c[2]), "+f"(c[3])
                 : "r"(a0), "r"(a1), "r"(a2), "r"(a3), "r"(b0), "r"(b1));
}
__device__ __forceinline__ u32 packbf(float lo, float hi) {  // {hi16, lo16}
    u32 r; asm("cvt.rn.bf16x2.f32 %0, %1, %2;" : "=r"(r) : "f"(hi), "f"(lo)); return r;
}

// ---------------------------------------------------------------------------
// Fused: X[256nodes,256f] @ Wc[256,64] (bf16 hi/lo 3-term HMMA) + gates + fc head
// ---------------------------------------------------------------------------
__global__ void __launch_bounds__(NTHR, 2)
fused_kernel(const float* __restrict__ x,
             const float* __restrict__ bz, const float* __restrict__ bh,
             const float* __restrict__ fc1w, const float* __restrict__ fc1b,
             const float* __restrict__ fc2w, const float* __restrict__ fc2b,
             float* __restrict__ out, int n)
{
    extern __shared__ char sm[];
    const u32 sb = s2u(sm);
    const int tid  = threadIdx.x;
    const int wid  = tid >> 5;
    const int lane = tid & 31;
    const int g    = lane >> 2;
    const int tg   = lane & 3;
    const int tile = blockIdx.x;

    // ---- stage W hi/lo into padded smem ----
    {
        const uint4* sH = (const uint4*)g_Whi;
        const uint4* sL = (const uint4*)g_Wlo;
        #pragma unroll
        for (int it = 0; it < 8; it++) {
            int e = tid + 256 * it;           // 2048 uint4 per array
            int row = e >> 5, c16 = e & 31;
            *(uint4*)(sm + OFF_WHI + row * W_STRIDE + c16 * 16) = sH[e];
            *(uint4*)(sm + OFF_WLO + row * W_STRIDE + c16 * 16) = sL[e];
        }
    }
    // ---- stage fc head + biases ----
    float* FC = (float*)(sm + OFF_FC);
    for (int i = tid; i < 1024; i += 256) FC[i] = fc1w[i];
    if (tid < 32) {
        FC[1024 + tid] = fc1b[tid];
        FC[1056 + tid] = fc2w[tid];
        FC[1089 + tid] = bz[tid];
        FC[1121 + tid] = bh[tid];
    }
    if (tid == 0) FC[1088] = fc2b[0];

    // ---- lane-derived ldmatrix address components ----
    const int rowA = (lane & 7) + ((lane >> 3) & 1) * 8;   // within m16
    const u32 aoff = (u32)(wid * 32 + rowA) * X_STRIDE + (u32)(lane >> 4) * 16;
    const int rowB = (lane & 7) + ((lane >> 4) & 1) * 8;   // within n16
    const u32 boff = (u32)rowB * W_STRIDE + (u32)((lane >> 3) & 1) * 16;

    float acc[2][8][4];
    #pragma unroll
    for (int mi = 0; mi < 2; mi++)
        #pragma unroll
        for (int nt = 0; nt < 8; nt++)
            #pragma unroll
            for (int r = 0; r < 4; r++) acc[mi][nt][r] = 0.f;

    // ---- K loop: 16 chunks of k16, register-prefetched ----
    float4 v[4];
    {   // prefetch chunk 0
        #pragma unroll
        for (int q = 0; q < 4; q++) {
            int f = tid + 256 * q;                 // 1024 float4 per chunk
            int node = f >> 2, k4 = (f & 3) * 4;
            int gn = tile * NPB + node;
            if (gn > n - 1) gn = n - 1;
            v[q] = *(const float4*)(x + (size_t)gn * NFEAT + k4);
        }
    }

    for (int c = 0; c < 16; c++) {
        if (c > 0) __syncthreads();                // prior HMMA done reading X
        // convert + store chunk c (hi/lo bf16)
        #pragma unroll
        for (int q = 0; q < 4; q++) {
            int f = tid + 256 * q;
            int node = f >> 2, k4 = (f & 3) * 4;
            float4 a = v[q];
            u32 h01 = packbf(a.x, a.y);
            u32 h23 = packbf(a.z, a.w);
            float r0 = a.x - __uint_as_float(h01 << 16);
            float r1 = a.y - __uint_as_float(h01 & 0xFFFF0000u);
            float r2 = a.z - __uint_as_float(h23 << 16);
            float r3 = a.w - __uint_as_float(h23 & 0xFFFF0000u);
            u32 l01 = packbf(r0, r1);
            u32 l23 = packbf(r2, r3);
            *(uint2*)(sm + OFF_XHI + node * X_STRIDE + k4 * 2) = make_uint2(h01, h23);
            *(uint2*)(sm + OFF_XLO + node * X_STRIDE + k4 * 2) = make_uint2(l01, l23);
        }
        __syncthreads();                           // stores visible (covers W staging @ c==0)

        if (c < 15) {                              // prefetch chunk c+1 (overlaps HMMA)
            int kbase = (c + 1) * 16;
            #pragma unroll
            for (int q = 0; q < 4; q++) {
                int f = tid + 256 * q;
                int node = f >> 2, k4 = (f & 3) * 4;
                int gn = tile * NPB + node;
                if (gn > n - 1) gn = n - 1;
                v[q] = *(const float4*)(x + (size_t)gn * NFEAT + kbase + k4);
            }
        }

        // ---- HMMA on chunk c ----
        u32 AH[2][4], AL[2][4];
        #pragma unroll
        for (int mi = 0; mi < 2; mi++) {
            ldsm4(sb + OFF_XHI + aoff + mi * 16 * X_STRIDE, AH[mi][0], AH[mi][1], AH[mi][2], AH[mi][3]);
            ldsm4(sb + OFF_XLO + aoff + mi * 16 * X_STRIDE, AL[mi][0], AL[mi][1], AL[mi][2], AL[mi][3]);
        }
        const u32 kb = (u32)c * 32;                // k16 * 2B into W rows
        #pragma unroll
        for (int nq = 0; nq < 4; nq++) {
            u32 bh0, bh1, bh2, bh3, bl0, bl1, bl2, bl3;
            ldsm4(sb + OFF_WHI + boff + nq * 16 * W_STRIDE + kb, bh0, bh1, bh2, bh3);
            ldsm4(sb + OFF_WLO + boff + nq * 16 * W_STRIDE + kb, bl0, bl1, bl2, bl3);
            #pragma unroll
            for (int mi = 0; mi < 2; mi++) {
                mma16816(acc[mi][2 * nq],     AH[mi][0], AH[mi][1], AH[mi][2], AH[mi][3], bh0, bh1);
                mma16816(acc[mi][2 * nq],     AH[mi][0], AH[mi][1], AH[mi][2], AH[mi][3], bl0, bl1);
                mma16816(acc[mi][2 * nq],     AL[mi][0], AL[mi][1], AL[mi][2], AL[mi][3], bh0, bh1);
                mma16816(acc[mi][2 * nq + 1], AH[mi][0], AH[mi][1], AH[mi][2], AH[mi][3], bh2, bh3);
                mma16816(acc[mi][2 * nq + 1], AH[mi][0], AH[mi][1], AH[mi][2], AH[mi][3], bl2, bl3);
                mma16816(acc[mi][2 * nq + 1], AL[mi][0], AL[mi][1], AL[mi][2], AL[mi][3], bh2, bh3);
            }
        }
    }

    // ---- stage pre-activations to smem (overlay on W region; X/FC intact) ----
    __syncthreads();                               // all LDSM reads of W done
    float* Hs = (float*)sm;                        // [256][66]
    #pragma unroll
    for (int mi = 0; mi < 2; mi++)
        #pragma unroll
        for (int nt = 0; nt < 8; nt++) {
            int col = nt * 8 + 2 * tg;
            int row = wid * 32 + mi * 16 + g;
            *(float2*)(Hs + row * 66 + col)       = make_float2(acc[mi][nt][0], acc[mi][nt][1]);
            *(float2*)(Hs + (row + 8) * 66 + col) = make_float2(acc[mi][nt][2], acc[mi][nt][3]);
        }
    __syncthreads();

    // ---- epilogue: one node per thread ----
    const float* hr = Hs + tid * 66;
    float h[32];
    #pragma unroll 8
    for (int j = 0; j < 32; j++) {
        float z  = 1.f / (1.f + __expf(-(hr[j] + FC[1089 + j])));
        float ht = tanhf(hr[32 + j] + FC[1121 + j]);
        h[j] = (1.f - z) * ht;                     // h0 = 0
    }
    float hid[32];
    #pragma unroll
    for (int i = 0; i < 32; i++) hid[i] = FC[1024 + i];
    #pragma unroll 4
    for (int j = 0; j < 32; j++) {
        float hj = h[j];
        #pragma unroll
        for (int i4 = 0; i4 < 8; i4++) {
            float4 w4 = *(const float4*)(FC + j * 32 + i4 * 4);
            hid[i4 * 4 + 0] = fmaf(hj, w4.x, hid[i4 * 4 + 0]);
            hid[i4 * 4 + 1] = fmaf(hj, w4.y, hid[i4 * 4 + 1]);
            hid[i4 * 4 + 2] = fmaf(hj, w4.z, hid[i4 * 4 + 2]);
            hid[i4 * 4 + 3] = fmaf(hj, w4.w, hid[i4 * 4 + 3]);
        }
    }
    float o = FC[1088];
    #pragma unroll
    for (int i = 0; i < 32; i++)
        o = fmaf(fmaxf(hid[i], 0.f), FC[1056 + i], o);

    int node = tile * NPB + tid;
    if (node < n) out[node] = 1.f / (1.f + __expf(-o));
}

// ---------------------------------------------------------------------------
// Launch. Inputs: x, edge_index(dead), w_z, b_z, w_r(dead), b_r(dead),
// w_h, b_h, fc1_w, fc1_b, fc2_w, fc2_b. Output: [N,1] float.
// ---------------------------------------------------------------------------
extern "C" void kernel_launch(void* const* d_in, const int* in_sizes, int n_in,
                              void* d_out, int out_size) {
    const float* x    = (const float*)d_in[0];
    const float* wz   = (const float*)d_in[2];
    const float* bz   = (const float*)d_in[3];
    const float* wh   = (const float*)d_in[6];
    const float* bh   = (const float*)d_in[7];
    const float* fc1w = (const float*)d_in[8];
    const float* fc1b = (const float*)d_in[9];
    const float* fc2w = (const float*)d_in[10];
    const float* fc2b = (const float*)d_in[11];
    float* out = (float*)d_out;

    const int n = out_size;
    const int ntiles = (n + NPB - 1) / NPB;

    prep_kernel<<<64, 256>>>(wz, wh);

    cudaFuncSetAttribute(fused_kernel, cudaFuncAttributeMaxDynamicSharedMemorySize, SMEM_BYTES);
    fused_kernel<<<ntiles, NTHR, SMEM_BYTES>>>(x, bz, bh, fc1w, fc1b, fc2w, fc2b, out, n);
}

// round 4
// speedup vs baseline: 1.8545x; 1.2124x over previous
#include <cuda_runtime.h>
#include <cuda_bf16.h>

typedef unsigned int u32;
typedef unsigned short u16;

#define NFEAT 256
#define NPB   256
#define NTHR  256

// ---- smem layout (bytes) ----
#define W_STRIDE 528                        // 64 rows x (512B data + 16B pad): ldmatrix conflict-free
#define OFF_WHI  0
#define OFF_WLO  (64 * W_STRIDE)            // 33792
#define OFF_FC   (2 * 64 * W_STRIDE)        // 67584  (== Hs overlay size: 256*66*4)
#define FC_FLOATS 1160
#define SMEM_BYTES (OFF_FC + FC_FLOATS * 4) // 72224

// W folded + split: [n=64][k=256] row-major bf16
__device__ __align__(16) u16 g_Whi[64 * 256];
__device__ __align__(16) u16 g_Wlo[64 * 256];

// ---------------------------------------------------------------------------
// Prep: wc[j][k] = (wz[0]+wz[1]) for j<32 else (wh[0]+wh[1]); x-rows only
// (h0 = 0 kills the H half of the concat and the whole r-gate).
// ---------------------------------------------------------------------------
__global__ void prep_kernel(const float* __restrict__ wz, const float* __restrict__ wh) {
    int idx = blockIdx.x * 256 + threadIdx.x;
    if (idx >= 64 * 256) return;
    int j = idx >> 8, k = idx & 255;
    const int D1 = 288 * 32;
    float wc = (j < 32) ? (wz[k * 32 + j] + wz[D1 + k * 32 + j])
                        : (wh[k * 32 + (j - 32)] + wh[D1 + k * 32 + (j - 32)]);
    __nv_bfloat16 h = __float2bfloat16(wc);
    __nv_bfloat16 l = __float2bfloat16(wc - __bfloat162float(h));
    g_Whi[j * 256 + k] = *reinterpret_cast<u16*>(&h);
    g_Wlo[j * 256 + k] = *reinterpret_cast<u16*>(&l);
}

// ---------------------------------------------------------------------------
// helpers
// ---------------------------------------------------------------------------
__device__ __forceinline__ u32 s2u(const void* p) {
    u32 a;
    asm("{ .reg .u64 t; cvta.to.shared.u64 t, %1; cvt.u32.u64 %0, t; }" : "=r"(a) : "l"(p));
    return a;
}
__device__ __forceinline__ void ldsm4(u32 a, u32& r0, u32& r1, u32& r2, u32& r3) {
    asm volatile("ldmatrix.sync.aligned.m8n8.x4.shared.b16 {%0,%1,%2,%3}, [%4];"
                 : "=r"(r0), "=r"(r1), "=r"(r2), "=r"(r3) : "r"(a));
}
__device__ __forceinline__ void mma16816(float* c, const u32* a, u32 b0, u32 b1) {
    asm volatile("mma.sync.aligned.m16n8k16.row.col.f32.bf16.bf16.f32 "
                 "{%0,%1,%2,%3},{%4,%5,%6,%7},{%8,%9},{%0,%1,%2,%3};"
                 : "+f"(c[0]), "+f"(c[1]), "+f"(c[2]), "+f"(c[3])
                 : "r"(a[0]), "r"(a[1]), "r"(a[2]), "r"(a[3]), "r"(b0), "r"(b1));
}
__device__ __forceinline__ u32 packbf(float lo, float hi) {  // reg = {hi16 | lo16}
    u32 r; asm("cvt.rn.bf16x2.f32 %0, %1, %2;" : "=r"(r) : "f"(hi), "f"(lo)); return r;
}

// load the 8 float2 A-fragment elements for chunk c (lane-mapped, no smem)
__device__ __forceinline__ void load_frag(float2* v, const float* const* p, int c) {
    const int kb = c * 16;
    #pragma unroll
    for (int mi = 0; mi < 2; mi++) {
        v[mi * 4 + 0] = *(const float2*)(p[mi * 2 + 0] + kb);      // row g,    k+0
        v[mi * 4 + 1] = *(const float2*)(p[mi * 2 + 1] + kb);      // row g+8,  k+0
        v[mi * 4 + 2] = *(const float2*)(p[mi * 2 + 0] + kb + 8);  // row g,    k+8
        v[mi * 4 + 3] = *(const float2*)(p[mi * 2 + 1] + kb + 8);  // row g+8,  k+8
    }
}

// ---------------------------------------------------------------------------
// Fused: X[256,256] @ Wc[256,64] (bf16 hi/lo 3-term HMMA, A direct from gmem)
// + GRU gates + fc head. No main-loop barriers.
// ---------------------------------------------------------------------------
__global__ void __launch_bounds__(NTHR, 2)
fused_kernel(const float* __restrict__ x,
             const float* __restrict__ bz, const float* __restrict__ bh,
             const float* __restrict__ fc1w, const float* __restrict__ fc1b,
             const float* __restrict__ fc2w, const float* __restrict__ fc2b,
             float* __restrict__ out, int n)
{
    extern __shared__ char sm[];
    const u32 sb = s2u(sm);
    const int tid  = threadIdx.x;
    const int wid  = tid >> 5;
    const int lane = tid & 31;
    const int g    = lane >> 2;
    const int tg   = lane & 3;
    const int tile = blockIdx.x;

    // ---- per-lane A row pointers (rows g, g+8, g+16, g+24 of warp m32 tile) ----
    const float* p[4];
    #pragma unroll
    for (int r4 = 0; r4 < 4; r4++) {
        int node = tile * NPB + wid * 32 + r4 * 8 + g;
        if (node > n - 1) node = n - 1;
        p[r4] = x + (size_t)node * NFEAT + 2 * tg;
    }

    // ---- prefetch chunk 0 (overlaps W staging) ----
    float2 v[8];
    load_frag(v, p, 0);

    // ---- stage W hi/lo into padded smem ----
    {
        const uint4* sH = (const uint4*)g_Whi;
        const uint4* sL = (const uint4*)g_Wlo;
        #pragma unroll
        for (int it = 0; it < 8; it++) {
            int e = tid + 256 * it;           // 2048 uint4 per array
            int row = e >> 5, c16 = e & 31;
            *(uint4*)(sm + OFF_WHI + row * W_STRIDE + c16 * 16) = sH[e];
            *(uint4*)(sm + OFF_WLO + row * W_STRIDE + c16 * 16) = sL[e];
        }
    }
    // ---- stage fc head + biases ----
    float* FC = (float*)(sm + OFF_FC);
    for (int i = tid; i < 1024; i += 256) FC[i] = fc1w[i];
    if (tid < 32) {
        FC[1024 + tid] = fc1b[tid];
        FC[1056 + tid] = fc2w[tid];
        FC[1089 + tid] = bz[tid];
        FC[1121 + tid] = bh[tid];
    }
    if (tid == 0) FC[1088] = fc2b[0];

    // ldmatrix address components for B (n16 x k16, x4), validated in R3
    const int rowB = (lane & 7) + ((lane >> 4) & 1) * 8;
    const u32 boff = (u32)rowB * W_STRIDE + (u32)((lane >> 3) & 1) * 16;

    float acc[2][8][4];
    #pragma unroll
    for (int mi = 0; mi < 2; mi++)
        #pragma unroll
        for (int nt = 0; nt < 8; nt++)
            #pragma unroll
            for (int r = 0; r < 4; r++) acc[mi][nt][r] = 0.f;

    __syncthreads();   // W/FC staged; last barrier until epilogue

    #pragma unroll 2
    for (int c = 0; c < 16; c++) {
        // prefetch next chunk (chunk 15 reloads itself; L1-hit, keeps code straight)
        float2 vn[8];
        load_frag(vn, p, c < 15 ? c + 1 : 15);

        // convert current chunk: fp32 -> bf16 hi + residual lo (in registers)
        u32 AH[2][4], AL[2][4];
        #pragma unroll
        for (int mi = 0; mi < 2; mi++)
            #pragma unroll
            for (int q = 0; q < 4; q++) {
                float2 a = v[mi * 4 + q];
                u32 hp = packbf(a.x, a.y);
                float r0 = a.x - __uint_as_float(hp << 16);
                float r1 = a.y - __uint_as_float(hp & 0xFFFF0000u);
                AH[mi][q] = hp;
                AL[mi][q] = packbf(r0, r1);
            }

        // B fragments from smem + 48 HMMAs (3-term: hh + hl + lh)
        const u32 kb = (u32)c * 32;
        #pragma unroll
        for (int nq = 0; nq < 4; nq++) {
            u32 bh0, bh1, bh2, bh3, bl0, bl1, bl2, bl3;
            ldsm4(sb + OFF_WHI + boff + nq * 16 * W_STRIDE + kb, bh0, bh1, bh2, bh3);
            ldsm4(sb + OFF_WLO + boff + nq * 16 * W_STRIDE + kb, bl0, bl1, bl2, bl3);
            #pragma unroll
            for (int mi = 0; mi < 2; mi++) {
                mma16816(acc[mi][2 * nq],     AH[mi], bh0, bh1);
                mma16816(acc[mi][2 * nq],     AH[mi], bl0, bl1);
                mma16816(acc[mi][2 * nq],     AL[mi], bh0, bh1);
                mma16816(acc[mi][2 * nq + 1], AH[mi], bh2, bh3);
                mma16816(acc[mi][2 * nq + 1], AH[mi], bl2, bl3);
                mma16816(acc[mi][2 * nq + 1], AL[mi], bh2, bh3);
            }
        }

        #pragma unroll
        for (int q = 0; q < 8; q++) v[q] = vn[q];
    }

    // ---- stage pre-activations to smem (overlay on W region; FC intact) ----
    __syncthreads();                               // all warps done reading W
    float* Hs = (float*)sm;                        // [256][66]
    #pragma unroll
    for (int mi = 0; mi < 2; mi++)
        #pragma unroll
        for (int nt = 0; nt < 8; nt++) {
            int col = nt * 8 + 2 * tg;
            int row = wid * 32 + mi * 16 + g;
            *(float2*)(Hs + row * 66 + col)       = make_float2(acc[mi][nt][0], acc[mi][nt][1]);
            *(float2*)(Hs + (row + 8) * 66 + col) = make_float2(acc[mi][nt][2], acc[mi][nt][3]);
        }
    __syncthreads();

    // ---- epilogue: one node per thread ----
    const float* hr = Hs + tid * 66;
    float h[32];
    #pragma unroll 8
    for (int j = 0; j < 32; j++) {
        float z  = 1.f / (1.f + __expf(-(hr[j] + FC[1089 + j])));
        float ht = tanhf(hr[32 + j] + FC[1121 + j]);
        h[j] = (1.f - z) * ht;                     // h0 = 0
    }
    float hid[32];
    #pragma unroll
    for (int i = 0; i < 32; i++) hid[i] = FC[1024 + i];
    #pragma unroll 4
    for (int j = 0; j < 32; j++) {
        float hj = h[j];
        #pragma unroll
        for (int i4 = 0; i4 < 8; i4++) {
            float4 w4 = *(const float4*)(FC + j * 32 + i4 * 4);
            hid[i4 * 4 + 0] = fmaf(hj, w4.x, hid[i4 * 4 + 0]);
            hid[i4 * 4 + 1] = fmaf(hj, w4.y, hid[i4 * 4 + 1]);
            hid[i4 * 4 + 2] = fmaf(hj, w4.z, hid[i4 * 4 + 2]);
            hid[i4 * 4 + 3] = fmaf(hj, w4.w, hid[i4 * 4 + 3]);
        }
    }
    float o = FC[1088];
    #pragma unroll
    for (int i = 0; i < 32; i++)
        o = fmaf(fmaxf(hid[i], 0.f), FC[1056 + i], o);

    int node = tile * NPB + tid;
    if (node < n) out[node] = 1.f / (1.f + __expf(-o));
}

// ---------------------------------------------------------------------------
// Launch. Inputs: x, edge_index(dead), w_z, b_z, w_r(dead), b_r(dead),
// w_h, b_h, fc1_w, fc1_b, fc2_w, fc2_b. Output: [N,1] float.
// ---------------------------------------------------------------------------
extern "C" void kernel_launch(void* const* d_in, const int* in_sizes, int n_in,
                              void* d_out, int out_size) {
    const float* x    = (const float*)d_in[0];
    const float* wz   = (const float*)d_in[2];
    const float* bz   = (const float*)d_in[3];
    const float* wh   = (const float*)d_in[6];
    const float* bh   = (const float*)d_in[7];
    const float* fc1w = (const float*)d_in[8];
    const float* fc1b = (const float*)d_in[9];
    const float* fc2w = (const float*)d_in[10];
    const float* fc2b = (const float*)d_in[11];
    float* out = (float*)d_out;

    const int n = out_size;
    const int ntiles = (n + NPB - 1) / NPB;

    prep_kernel<<<64, 256>>>(wz, wh);

    cudaFuncSetAttribute(fused_kernel, cudaFuncAttributeMaxDynamicSharedMemorySize, SMEM_BYTES);
    fused_kernel<<<ntiles, NTHR, SMEM_BYTES>>>(x, bz, bh, fc1w, fc1b, fc2w, fc2b, out, n);
}

// round 5
// speedup vs baseline: 2.3530x; 1.2688x over previous
#include <cuda_runtime.h>
#include <cuda_fp16.h>

typedef unsigned int u32;
typedef unsigned short u16;

#define NFEAT 256
#define NPB   256
#define NTHR  256

// ---- smem layout (bytes) ----
#define W_STRIDE 528                        // 64 rows x (512B data + 16B pad): ldmatrix conflict-free
#define OFF_WH   0
#define OFF_FC   67584                      // Hs overlay needs 256*66*4 = 67584 bytes
#define FC_FLOATS 1160
#define SMEM_BYTES (OFF_FC + FC_FLOATS * 4) // 72224 -> 2 CTAs/SM

// W folded: [n=64][k=256] row-major fp16
__device__ __align__(16) u16 g_Wh[64 * 256];

// ---------------------------------------------------------------------------
// Prep: wc[j][k] = (wz[0]+wz[1]) for j<32 else (wh[0]+wh[1]); x-rows only
// (h0 = 0 kills the H half of the concat and the whole r-gate).
// ---------------------------------------------------------------------------
__global__ void prep_kernel(const float* __restrict__ wz, const float* __restrict__ wh) {
    int idx = blockIdx.x * 256 + threadIdx.x;
    if (idx >= 64 * 256) return;
    int j = idx >> 8, k = idx & 255;
    const int D1 = 288 * 32;
    float wc = (j < 32) ? (wz[k * 32 + j] + wz[D1 + k * 32 + j])
                        : (wh[k * 32 + (j - 32)] + wh[D1 + k * 32 + (j - 32)]);
    __half h = __float2half_rn(wc);
    g_Wh[j * 256 + k] = *reinterpret_cast<u16*>(&h);
}

// ---------------------------------------------------------------------------
// helpers
// ---------------------------------------------------------------------------
__device__ __forceinline__ u32 s2u(const void* p) {
    u32 a;
    asm("{ .reg .u64 t; cvta.to.shared.u64 t, %1; cvt.u32.u64 %0, t; }" : "=r"(a) : "l"(p));
    return a;
}
__device__ __forceinline__ void ldsm4(u32 a, u32& r0, u32& r1, u32& r2, u32& r3) {
    asm volatile("ldmatrix.sync.aligned.m8n8.x4.shared.b16 {%0,%1,%2,%3}, [%4];"
                 : "=r"(r0), "=r"(r1), "=r"(r2), "=r"(r3) : "r"(a));
}
__device__ __forceinline__ void mma16816(float* c, const u32* a, u32 b0, u32 b1) {
    asm volatile("mma.sync.aligned.m16n8k16.row.col.f32.f16.f16.f32 "
                 "{%0,%1,%2,%3},{%4,%5,%6,%7},{%8,%9},{%0,%1,%2,%3};"
                 : "+f"(c[0]), "+f"(c[1]), "+f"(c[2]), "+f"(c[3])
                 : "r"(a[0]), "r"(a[1]), "r"(a[2]), "r"(a[3]), "r"(b0), "r"(b1));
}
__device__ __forceinline__ u32 packh(float lo, float hi) {  // reg = {hi16 | lo16}
    u32 r; asm("cvt.rn.f16x2.f32 %0, %1, %2;" : "=r"(r) : "f"(hi), "f"(lo)); return r;
}

// ---------------------------------------------------------------------------
// Fused: X[256,256] @ Wc[256,64] (single-pass fp16 HMMA, A direct from gmem
// via LDG.128 + xor-1 shuffle) + GRU gates + fc head. No main-loop barriers.
// ---------------------------------------------------------------------------
__global__ void __launch_bounds__(NTHR, 2)
fused_kernel(const float* __restrict__ x,
             const float* __restrict__ bz, const float* __restrict__ bh,
             const float* __restrict__ fc1w, const float* __restrict__ fc1b,
             const float* __restrict__ fc2w, const float* __restrict__ fc2b,
             float* __restrict__ out, int n)
{
    extern __shared__ char sm[];
    const u32 sb = s2u(sm);
    const int tid  = threadIdx.x;
    const int wid  = tid >> 5;
    const int lane = tid & 31;
    const int g    = lane >> 2;
    const int tg   = lane & 3;
    const bool ev  = (lane & 1) == 0;
    const int tile = blockIdx.x;

    // per-lane k offset within a chunk for the float4 load:
    // tg=0 -> k0-3, tg=1 -> k8-11, tg=2 -> k4-7, tg=3 -> k12-15
    const int koff = 8 * (tg & 1) + 4 * (tg >> 1);

    // per-lane A row pointers (rows g, g+8, g+16, g+24 of warp m32 tile)
    const float* p[4];
    #pragma unroll
    for (int r4 = 0; r4 < 4; r4++) {
        int node = tile * NPB + wid * 32 + r4 * 8 + g;
        if (node > n - 1) node = n - 1;
        p[r4] = x + (size_t)node * NFEAT + koff;
    }

    // prefetch chunk 0 (overlaps W staging)
    float4 v[4];
    #pragma unroll
    for (int r4 = 0; r4 < 4; r4++) v[r4] = *(const float4*)(p[r4]);

    // ---- stage W into padded smem ----
    {
        const uint4* sH = (const uint4*)g_Wh;
        #pragma unroll
        for (int it = 0; it < 8; it++) {
            int e = tid + 256 * it;           // 2048 uint4
            int row = e >> 5, c16 = e & 31;
            *(uint4*)(sm + OFF_WH + row * W_STRIDE + c16 * 16) = sH[e];
        }
    }
    // ---- stage fc head + biases ----
    float* FC = (float*)(sm + OFF_FC);
    for (int i = tid; i < 1024; i += 256) FC[i] = fc1w[i];
    if (tid < 32) {
        FC[1024 + tid] = fc1b[tid];
        FC[1056 + tid] = fc2w[tid];
        FC[1089 + tid] = bz[tid];
        FC[1121 + tid] = bh[tid];
    }
    if (tid == 0) FC[1088] = fc2b[0];

    // ldmatrix address components for B (n16 x k16, x4), validated R3/R4
    const int rowB = (lane & 7) + ((lane >> 4) & 1) * 8;
    const u32 boff = (u32)rowB * W_STRIDE + (u32)((lane >> 3) & 1) * 16;

    float acc[2][8][4];
    #pragma unroll
    for (int mi = 0; mi < 2; mi++)
        #pragma unroll
        for (int nt = 0; nt < 8; nt++)
            #pragma unroll
            for (int r = 0; r < 4; r++) acc[mi][nt][r] = 0.f;

    __syncthreads();   // W/FC staged; last barrier until epilogue

    #pragma unroll 2
    for (int c = 0; c < 16; c++) {
        // prefetch next chunk (chunk 15 reloads itself; L1-hit)
        float4 vn[4];
        {
            int cn = (c < 15) ? c + 1 : 15;
            #pragma unroll
            for (int r4 = 0; r4 < 4; r4++)
                vn[r4] = *(const float4*)(p[r4] + cn * 16);
        }

        // redistribute via xor-1 shuffle, convert to fp16 A fragments
        // AKL[r4] = {x[row, 2tg], x[row, 2tg+1]}, AKH[r4] = same at k+8
        u32 AKL[4], AKH[4];
        #pragma unroll
        for (int r4 = 0; r4 < 4; r4++) {
            float4 f = v[r4];
            float s1 = ev ? f.z : f.x;
            float s2 = ev ? f.w : f.y;
            float r1 = __shfl_xor_sync(0xffffffffu, s1, 1);
            float r2 = __shfl_xor_sync(0xffffffffu, s2, 1);
            float lx = ev ? f.x : r1;
            float ly = ev ? f.y : r2;
            float hx = ev ? r1 : f.z;
            float hy = ev ? r2 : f.w;
            AKL[r4] = packh(lx, ly);
            AKH[r4] = packh(hx, hy);
        }
        u32 A0[4] = {AKL[0], AKL[1], AKH[0], AKH[1]};   // rows g, g+8
        u32 A1[4] = {AKL[2], AKL[3], AKH[2], AKH[3]};   // rows g+16, g+24

        // B fragments from smem + 16 HMMAs
        const u32 kb = (u32)c * 32;
        #pragma unroll
        for (int nq = 0; nq < 4; nq++) {
            u32 b0, b1, b2, b3;
            ldsm4(sb + OFF_WH + boff + nq * 16 * W_STRIDE + kb, b0, b1, b2, b3);
            mma16816(acc[0][2 * nq],     A0, b0, b1);
            mma16816(acc[0][2 * nq + 1], A0, b2, b3);
            mma16816(acc[1][2 * nq],     A1, b0, b1);
            mma16816(acc[1][2 * nq + 1], A1, b2, b3);
        }

        #pragma unroll
        for (int r4 = 0; r4 < 4; r4++) v[r4] = vn[r4];
    }

    // ---- stage pre-activations to smem (overlay on W region; FC intact) ----
    __syncthreads();                               // all warps done reading W
    float* Hs = (float*)sm;                        // [256][66]
    #pragma unroll
    for (int mi = 0; mi < 2; mi++)
        #pragma unroll
        for (int nt = 0; nt < 8; nt++) {
            int col = nt * 8 + 2 * tg;
            int row = wid * 32 + mi * 16 + g;
            *(float2*)(Hs + row * 66 + col)       = make_float2(acc[mi][nt][0], acc[mi][nt][1]);
            *(float2*)(Hs + (row + 8) * 66 + col) = make_float2(acc[mi][nt][2], acc[mi][nt][3]);
        }
    __syncthreads();

    // ---- epilogue: one node per thread ----
    const float* hr = Hs + tid * 66;
    float h[32];
    #pragma unroll 8
    for (int j = 0; j < 32; j++) {
        float z  = 1.f / (1.f + __expf(-(hr[j] + FC[1089 + j])));
        float ht = tanhf(hr[32 + j] + FC[1121 + j]);
        h[j] = (1.f - z) * ht;                     // h0 = 0
    }
    float hid[32];
    #pragma unroll
    for (int i = 0; i < 32; i++) hid[i] = FC[1024 + i];
    #pragma unroll 4
    for (int j = 0; j < 32; j++) {
        float hj = h[j];
        #pragma unroll
        for (int i4 = 0; i4 < 8; i4++) {
            float4 w4 = *(const float4*)(FC + j * 32 + i4 * 4);
            hid[i4 * 4 + 0] = fmaf(hj, w4.x, hid[i4 * 4 + 0]);
            hid[i4 * 4 + 1] = fmaf(hj, w4.y, hid[i4 * 4 + 1]);
            hid[i4 * 4 + 2] = fmaf(hj, w4.z, hid[i4 * 4 + 2]);
            hid[i4 * 4 + 3] = fmaf(hj, w4.w, hid[i4 * 4 + 3]);
        }
    }
    float o = FC[1088];
    #pragma unroll
    for (int i = 0; i < 32; i++)
        o = fmaf(fmaxf(hid[i], 0.f), FC[1056 + i], o);

    int node = tile * NPB + tid;
    if (node < n) out[node] = 1.f / (1.f + __expf(-o));
}

// ---------------------------------------------------------------------------
// Launch. Inputs: x, edge_index(dead), w_z, b_z, w_r(dead), b_r(dead),
// w_h, b_h, fc1_w, fc1_b, fc2_w, fc2_b. Output: [N,1] float.
// ---------------------------------------------------------------------------
extern "C" void kernel_launch(void* const* d_in, const int* in_sizes, int n_in,
                              void* d_out, int out_size) {
    const float* x    = (const float*)d_in[0];
    const float* wz   = (const float*)d_in[2];
    const float* bz   = (const float*)d_in[3];
    const float* wh   = (const float*)d_in[6];
    const float* bh   = (const float*)d_in[7];
    const float* fc1w = (const float*)d_in[8];
    const float* fc1b = (const float*)d_in[9];
    const float* fc2w = (const float*)d_in[10];
    const float* fc2b = (const float*)d_in[11];
    float* out = (float*)d_out;

    const int n = out_size;
    const int ntiles = (n + NPB - 1) / NPB;

    prep_kernel<<<64, 256>>>(wz, wh);

    cudaFuncSetAttribute(fused_kernel, cudaFuncAttributeMaxDynamicSharedMemorySize, SMEM_BYTES);
    fused_kernel<<<ntiles, NTHR, SMEM_BYTES>>>(x, bz, bh, fc1w, fc1b, fc2w, fc2b, out, n);
}

// round 6
// speedup vs baseline: 3.0153x; 1.2815x over previous
#include <cuda_runtime.h>
#include <cuda_fp16.h>

typedef unsigned int u32;
typedef unsigned short u16;

#define NFEAT 256
#define NPB   256
#define NTHR  256

// ---- smem layout (bytes) ----
#define W_STRIDE 528                        // 64 rows x (512B + 16B pad): ldmatrix conflict-free
#define OFF_WH   0
#define OFF_FC   (64 * W_STRIDE)            // 33792
// FC region (floats/u32): fc1q[512 u32] | fc2w[32] | fc1b[32] | bz[32] | bh[32] | fc2b[1]
#define FCQ   0
#define FW2   512
#define FB1   544
#define FBZ   576
#define FBH   608
#define FB2   640
#define SMEM_BYTES (OFF_FC + 642 * 4)       // ~36.4KB -> 2 CTAs/SM (reg-limited anyway)

// W folded: [n=64][k=256] row-major fp16
__device__ __align__(16) u16 g_Wh[64 * 256];
// fc1 packed for B-fragments: fc1q[jp][i] = {lo: fc1[2jp][i], hi: fc1[2jp+1][i]} fp16
__device__ __align__(16) u32 g_fc1q[16 * 32];

// ---------------------------------------------------------------------------
// Prep: fold wc[j][k] = (wz[0]+wz[1]) | (wh[0]+wh[1]) (x-rows only; h0=0 kills
// the H half of the concat and the r-gate). Also pack fc1 into b-frag layout.
// ---------------------------------------------------------------------------
__global__ void prep_kernel(const float* __restrict__ wz, const float* __restrict__ wh,
                            const float* __restrict__ fc1w) {
    int idx = blockIdx.x * 256 + threadIdx.x;
    if (idx < 64 * 256) {
        int j = idx >> 8, k = idx & 255;
        const int D1 = 288 * 32;
        float wc = (j < 32) ? (wz[k * 32 + j] + wz[D1 + k * 32 + j])
                            : (wh[k * 32 + (j - 32)] + wh[D1 + k * 32 + (j - 32)]);
        __half h = __float2half_rn(wc);
        g_Wh[j * 256 + k] = *reinterpret_cast<u16*>(&h);
    }
    if (idx < 512) {
        int jp = idx >> 5, i = idx & 31;
        __half lo = __float2half_rn(fc1w[(2 * jp) * 32 + i]);
        __half hi = __float2half_rn(fc1w[(2 * jp + 1) * 32 + i]);
        g_fc1q[idx] = ((u32)*reinterpret_cast<u16*>(&hi) << 16) | *reinterpret_cast<u16*>(&lo);
    }
}

// ---------------------------------------------------------------------------
// helpers
// ---------------------------------------------------------------------------
__device__ __forceinline__ u32 s2u(const void* p) {
    u32 a;
    asm("{ .reg .u64 t; cvta.to.shared.u64 t, %1; cvt.u32.u64 %0, t; }" : "=r"(a) : "l"(p));
    return a;
}
__device__ __forceinline__ void ldsm4(u32 a, u32& r0, u32& r1, u32& r2, u32& r3) {
    asm volatile("ldmatrix.sync.aligned.m8n8.x4.shared.b16 {%0,%1,%2,%3}, [%4];"
                 : "=r"(r0), "=r"(r1), "=r"(r2), "=r"(r3) : "r"(a));
}
__device__ __forceinline__ void mma16816(float* c, const u32* a, u32 b0, u32 b1) {
    asm volatile("mma.sync.aligned.m16n8k16.row.col.f32.f16.f16.f32 "
                 "{%0,%1,%2,%3},{%4,%5,%6,%7},{%8,%9},{%0,%1,%2,%3};"
                 : "+f"(c[0]), "+f"(c[1]), "+f"(c[2]), "+f"(c[3])
                 : "r"(a[0]), "r"(a[1]), "r"(a[2]), "r"(a[3]), "r"(b0), "r"(b1));
}
__device__ __forceinline__ u32 packh(float lo, float hi) {  // reg = {hi16 | lo16}
    u32 r; asm("cvt.rn.f16x2.f32 %0, %1, %2;" : "=r"(r) : "f"(hi), "f"(lo)); return r;
}
__device__ __forceinline__ float sigf(float x) {            // 1/(1+e^-x)
    return 1.f / (1.f + __expf(-x));
}
__device__ __forceinline__ float tanhg(float x) {           // exact identity, overflow-safe
    float e = __expf(-2.f * fabsf(x));
    float t = (1.f - e) / (1.f + e);
    return copysignf(t, x);
}

// ---------------------------------------------------------------------------
// Fused: X[256,256] @ Wc[256,64] fp16 HMMA (A direct from gmem via LDG.128 +
// xor-1 shuffle) + register-resident GRU gates + tensor-core fc head.
// Exactly ONE __syncthreads in the whole kernel.
// ---------------------------------------------------------------------------
__global__ void __launch_bounds__(NTHR, 2)
fused_kernel(const float* __restrict__ x,
             const float* __restrict__ bz, const float* __restrict__ bh,
             const float* __restrict__ fc1b,
             const float* __restrict__ fc2w, const float* __restrict__ fc2b,
             float* __restrict__ out, int n)
{
    extern __shared__ char sm[];
    const u32 sb = s2u(sm);
    const int tid  = threadIdx.x;
    const int wid  = tid >> 5;
    const int lane = tid & 31;
    const int g    = lane >> 2;
    const int tg   = lane & 3;
    const bool ev  = (lane & 1) == 0;
    const int tile = blockIdx.x;

    // per-lane k offset: tg=0 -> k0-3, tg=1 -> k8-11, tg=2 -> k4-7, tg=3 -> k12-15
    const int koff = 8 * (tg & 1) + 4 * (tg >> 1);

    // per-lane A row pointers (rows g, g+8, g+16, g+24 of warp m32 tile)
    const float* p[4];
    #pragma unroll
    for (int r4 = 0; r4 < 4; r4++) {
        int node = tile * NPB + wid * 32 + r4 * 8 + g;
        if (node > n - 1) node = n - 1;
        p[r4] = x + (size_t)node * NFEAT + koff;
    }

    // prefetch chunk 0 (overlaps staging)
    float4 v[4];
    #pragma unroll
    for (int r4 = 0; r4 < 4; r4++) v[r4] = *(const float4*)(p[r4]);

    // ---- stage W into padded smem ----
    {
        const uint4* sH = (const uint4*)g_Wh;
        #pragma unroll
        for (int it = 0; it < 8; it++) {
            int e = tid + 256 * it;
            int row = e >> 5, c16 = e & 31;
            *(uint4*)(sm + OFF_WH + row * W_STRIDE + c16 * 16) = sH[e];
        }
    }
    // ---- stage fc head + biases ----
    u32* FCq = (u32*)(sm + OFF_FC);
    float* FCf = (float*)(sm + OFF_FC);
    FCq[FCQ + tid] = g_fc1q[tid & 511];            // 512 entries (tid>=512 n/a; NTHR=256 -> 2x)
    FCq[FCQ + 256 + tid] = g_fc1q[256 + (tid & 255)];
    if (tid < 32) {
        FCf[FW2 + tid] = fc2w[tid];
        FCf[FB1 + tid] = fc1b[tid];
        FCf[FBZ + tid] = bz[tid];
        FCf[FBH + tid] = bh[tid];
    }
    if (tid == 0) FCf[FB2] = fc2b[0];

    // ldmatrix address for B (n16 x k16, x4), validated R3-R5
    const int rowB = (lane & 7) + ((lane >> 4) & 1) * 8;
    const u32 boff = (u32)rowB * W_STRIDE + (u32)((lane >> 3) & 1) * 16;

    float acc[2][8][4];
    #pragma unroll
    for (int mi = 0; mi < 2; mi++)
        #pragma unroll
        for (int nt = 0; nt < 8; nt++)
            #pragma unroll
            for (int r = 0; r < 4; r++) acc[mi][nt][r] = 0.f;

    __syncthreads();   // the only barrier

    #pragma unroll 2
    for (int c = 0; c < 16; c++) {
        float4 vn[4];
        {
            int cn = (c < 15) ? c + 1 : 15;
            #pragma unroll
            for (int r4 = 0; r4 < 4; r4++)
                vn[r4] = *(const float4*)(p[r4] + cn * 16);
        }

        // redistribute via xor-1 shuffle, convert to fp16 A fragments
        u32 AKL[4], AKH[4];
        #pragma unroll
        for (int r4 = 0; r4 < 4; r4++) {
            float4 f = v[r4];
            float s1 = ev ? f.z : f.x;
            float s2 = ev ? f.w : f.y;
            float r1 = __shfl_xor_sync(0xffffffffu, s1, 1);
            float r2 = __shfl_xor_sync(0xffffffffu, s2, 1);
            AKL[r4] = packh(ev ? f.x : r1, ev ? f.y : r2);
            AKH[r4] = packh(ev ? r1 : f.z, ev ? r2 : f.w);
        }
        u32 A0[4] = {AKL[0], AKL[1], AKH[0], AKH[1]};   // rows g, g+8
        u32 A1[4] = {AKL[2], AKL[3], AKH[2], AKH[3]};   // rows g+16, g+24

        const u32 kb = (u32)c * 32;
        #pragma unroll
        for (int nq = 0; nq < 4; nq++) {
            u32 b0, b1, b2, b3;
            ldsm4(sb + OFF_WH + boff + nq * 16 * W_STRIDE + kb, b0, b1, b2, b3);
            mma16816(acc[0][2 * nq],     A0, b0, b1);
            mma16816(acc[0][2 * nq + 1], A0, b2, b3);
            mma16816(acc[1][2 * nq],     A1, b0, b1);
            mma16816(acc[1][2 * nq + 1], A1, b2, b3);
        }

        #pragma unroll
        for (int r4 = 0; r4 < 4; r4++) v[r4] = vn[r4];
    }

    // ======================= register-resident epilogue =======================
    // cols: acc[mi][nt] covers cols 8nt+2tg(+1), rows g (c0,c1), g+8 (c2,c3).
    // z-gate = cols 0..31 (nt 0..3), h-tilde = cols 32..63 (nt+4). Same thread
    // holds matching pairs -> gates need no data movement at all.
    u32 Afc[2][2][4];                                  // fc1 A-fragments [mi][k16][4]
    #pragma unroll
    for (int mi = 0; mi < 2; mi++)
        #pragma unroll
        for (int c = 0; c < 2; c++)
            #pragma unroll
            for (int half = 0; half < 2; half++) {
                int ntz = 2 * c + half;
                float2 bzv = *(float2*)(FCf + FBZ + 8 * ntz + 2 * tg);
                float2 bhv = *(float2*)(FCf + FBH + 8 * ntz + 2 * tg);
                float h0 = (1.f - sigf(acc[mi][ntz][0] + bzv.x)) * tanhg(acc[mi][ntz + 4][0] + bhv.x);
                float h1 = (1.f - sigf(acc[mi][ntz][1] + bzv.y)) * tanhg(acc[mi][ntz + 4][1] + bhv.y);
                float h2 = (1.f - sigf(acc[mi][ntz][2] + bzv.x)) * tanhg(acc[mi][ntz + 4][2] + bhv.x);
                float h3 = (1.f - sigf(acc[mi][ntz][3] + bzv.y)) * tanhg(acc[mi][ntz + 4][3] + bhv.y);
                Afc[mi][c][half * 2 + 0] = packh(h0, h1);   // rows g   (a0 / a2)
                Afc[mi][c][half * 2 + 1] = packh(h2, h3);   // rows g+8 (a1 / a3)
            }

    // fc1: hidden[m,32] = h[m,32] @ fc1w[32,32] + b1 via 16 HMMAs (fp32 C)
    float a2[2][4][4];
    #pragma unroll
    for (int q = 0; q < 4; q++) {
        float2 b1v = *(float2*)(FCf + FB1 + 8 * q + 2 * tg);
        #pragma unroll
        for (int mi = 0; mi < 2; mi++) {
            a2[mi][q][0] = b1v.x; a2[mi][q][1] = b1v.y;
            a2[mi][q][2] = b1v.x; a2[mi][q][3] = b1v.y;
        }
    }
    #pragma unroll
    for (int c = 0; c < 2; c++)
        #pragma unroll
        for (int q = 0; q < 4; q++) {
            u32 bf0 = FCq[FCQ + (tg + 8 * c) * 32 + g + 8 * q];
            u32 bf1 = FCq[FCQ + (tg + 4 + 8 * c) * 32 + g + 8 * q];
            mma16816(a2[0][q], Afc[0][c], bf0, bf1);
            mma16816(a2[1][q], Afc[1][c], bf0, bf1);
        }

    // fc2 + sigmoid: o[m] = sigma( sum_n relu(hidden[m,n]) * fc2w[n] + b2 )
    const float b2 = FCf[FB2];
    #pragma unroll
    for (int mi = 0; mi < 2; mi++) {
        float og = 0.f, og8 = 0.f;
        #pragma unroll
        for (int q = 0; q < 4; q++) {
            float2 w2 = *(float2*)(FCf + FW2 + 8 * q + 2 * tg);
            og  = fmaf(fmaxf(a2[mi][q][0], 0.f), w2.x, og);
            og  = fmaf(fmaxf(a2[mi][q][1], 0.f), w2.y, og);
            og8 = fmaf(fmaxf(a2[mi][q][2], 0.f), w2.x, og8);
            og8 = fmaf(fmaxf(a2[mi][q][3], 0.f), w2.y, og8);
        }
        og  += __shfl_xor_sync(0xffffffffu, og, 1);
        og  += __shfl_xor_sync(0xffffffffu, og, 2);
        og8 += __shfl_xor_sync(0xffffffffu, og8, 1);
        og8 += __shfl_xor_sync(0xffffffffu, og8, 2);
        if (tg == 0) {
            int node = tile * NPB + wid * 32 + mi * 16 + g;
            if (node < n)     out[node]     = sigf(og + b2);
            if (node + 8 < n) out[node + 8] = sigf(og8 + b2);
        }
    }
}

// ---------------------------------------------------------------------------
// Launch. Inputs: x, edge_index(dead), w_z, b_z, w_r(dead), b_r(dead),
// w_h, b_h, fc1_w, fc1_b, fc2_w, fc2_b. Output: [N,1] float.
// ---------------------------------------------------------------------------
extern "C" void kernel_launch(void* const* d_in, const int* in_sizes, int n_in,
                              void* d_out, int out_size) {
    const float* x    = (const float*)d_in[0];
    const float* wz   = (const float*)d_in[2];
    const float* bz   = (const float*)d_in[3];
    const float* wh   = (const float*)d_in[6];
    const float* bh   = (const float*)d_in[7];
    const float* fc1w = (const float*)d_in[8];
    const float* fc1b = (const float*)d_in[9];
    const float* fc2w = (const float*)d_in[10];
    const float* fc2b = (const float*)d_in[11];
    float* out = (float*)d_out;

    const int n = out_size;
    const int ntiles = (n + NPB - 1) / NPB;

    prep_kernel<<<64, 256>>>(wz, wh, fc1w);

    cudaFuncSetAttribute(fused_kernel, cudaFuncAttributeMaxDynamicSharedMemorySize, SMEM_BYTES);
    fused_kernel<<<ntiles, NTHR, SMEM_BYTES>>>(x, bz, bh, fc1b, fc2w, fc2b, out, n);
}

// round 7
// speedup vs baseline: 3.4746x; 1.1523x over previous
#include <cuda_runtime.h>
#include <cuda_fp16.h>

typedef unsigned int u32;
typedef unsigned short u16;

#define NFEAT 256
#define NPB   256
#define NTHR  256

// ---- smem layout (bytes) ----
#define W_STRIDE 528                        // 64 rows x (512B + 16B pad): ldmatrix conflict-free
#define OFF_WH   0
#define OFF_X    33792                      // X ring: 3 stages x (8 warps x 32 rows x 64B)
#define XSTAGE   16384
#define OFF_FC   (OFF_X + 3 * XSTAGE)       // 82944
// FC region (floats/u32): fc1q[512 u32] | fc2w[32] | fc1b[32] | bz[32] | bh[32] | fc2b[1]
#define FCQ   0
#define FW2   512
#define FB1   544
#define FBZ   576
#define FBH   608
#define FB2   640
#define SMEM_BYTES (OFF_FC + 642 * 4)       // 85512 -> 2 CTAs/SM

// W folded: [n=64][k=256] row-major fp16
__device__ __align__(16) u16 g_Wh[64 * 256];
// fc1 packed for B-fragments: fc1q[jp][i] = {lo: fc1[2jp][i], hi: fc1[2jp+1][i]} fp16
__device__ __align__(16) u32 g_fc1q[16 * 32];

// ---------------------------------------------------------------------------
// Prep: fold wc[j][k] = (wz[0]+wz[1]) | (wh[0]+wh[1]) (x-rows only; h0=0 kills
// the H half of the concat and the r-gate). Also pack fc1 into b-frag layout.
// ---------------------------------------------------------------------------
__global__ void prep_kernel(const float* __restrict__ wz, const float* __restrict__ wh,
                            const float* __restrict__ fc1w) {
    int idx = blockIdx.x * 256 + threadIdx.x;
    if (idx < 64 * 256) {
        int j = idx >> 8, k = idx & 255;
        const int D1 = 288 * 32;
        float wc = (j < 32) ? (wz[k * 32 + j] + wz[D1 + k * 32 + j])
                            : (wh[k * 32 + (j - 32)] + wh[D1 + k * 32 + (j - 32)]);
        __half h = __float2half_rn(wc);
        g_Wh[j * 256 + k] = *reinterpret_cast<u16*>(&h);
    }
    if (idx < 512) {
        int jp = idx >> 5, i = idx & 31;
        __half lo = __float2half_rn(fc1w[(2 * jp) * 32 + i]);
        __half hi = __float2half_rn(fc1w[(2 * jp + 1) * 32 + i]);
        g_fc1q[idx] = ((u32)*reinterpret_cast<u16*>(&hi) << 16) | *reinterpret_cast<u16*>(&lo);
    }
}

// ---------------------------------------------------------------------------
// helpers
// ---------------------------------------------------------------------------
__device__ __forceinline__ u32 s2u(const void* p) {
    u32 a;
    asm("{ .reg .u64 t; cvta.to.shared.u64 t, %1; cvt.u32.u64 %0, t; }" : "=r"(a) : "l"(p));
    return a;
}
__device__ __forceinline__ void ldsm4(u32 a, u32& r0, u32& r1, u32& r2, u32& r3) {
    asm volatile("ldmatrix.sync.aligned.m8n8.x4.shared.b16 {%0,%1,%2,%3}, [%4];"
                 : "=r"(r0), "=r"(r1), "=r"(r2), "=r"(r3) : "r"(a));
}
__device__ __forceinline__ void mma16816(float* c, const u32* a, u32 b0, u32 b1) {
    asm volatile("mma.sync.aligned.m16n8k16.row.col.f32.f16.f16.f32 "
                 "{%0,%1,%2,%3},{%4,%5,%6,%7},{%8,%9},{%0,%1,%2,%3};"
                 : "+f"(c[0]), "+f"(c[1]), "+f"(c[2]), "+f"(c[3])
                 : "r"(a[0]), "r"(a[1]), "r"(a[2]), "r"(a[3]), "r"(b0), "r"(b1));
}
__device__ __forceinline__ u32 packh(float lo, float hi) {  // reg = {hi16 | lo16}
    u32 r; asm("cvt.rn.f16x2.f32 %0, %1, %2;" : "=r"(r) : "f"(hi), "f"(lo)); return r;
}
__device__ __forceinline__ void cpasync16(u32 dst, const void* src) {
    asm volatile("cp.async.cg.shared.global [%0], [%1], 16;" :: "r"(dst), "l"(src));
}
__device__ __forceinline__ void cp_commit() {
    asm volatile("cp.async.commit_group;" ::: "memory");
}
__device__ __forceinline__ void cp_wait2() {
    asm volatile("cp.async.wait_group 2;" ::: "memory");
}
__device__ __forceinline__ float sigf(float x) { return 1.f / (1.f + __expf(-x)); }
__device__ __forceinline__ float tanhg(float x) {
    float e = __expf(-2.f * fabsf(x));
    return copysignf((1.f - e) / (1.f + e), x);
}

// ---------------------------------------------------------------------------
// Fused: X[256,256] @ Wc[256,64] fp16 HMMA. X streamed via per-warp cp.async
// 3-stage smem ring (no cross-warp sync), register-resident GRU gates +
// tensor-core fc head. ONE __syncthreads in the whole kernel.
// ---------------------------------------------------------------------------
__global__ void __launch_bounds__(NTHR, 2)
fused_kernel(const float* __restrict__ x,
             const float* __restrict__ bz, const float* __restrict__ bh,
             const float* __restrict__ fc1b,
             const float* __restrict__ fc2w, const float* __restrict__ fc2b,
             float* __restrict__ out, int n)
{
    extern __shared__ char sm[];
    const u32 sb = s2u(sm);
    const int tid  = threadIdx.x;
    const int wid  = tid >> 5;
    const int lane = tid & 31;
    const int g    = lane >> 2;
    const int tg   = lane & 3;
    const int u    = lane & 3;         // cp.async 16B-unit within row
    const bool ev  = (lane & 1) == 0;
    const int tile = blockIdx.x;

    // per-lane k offset for the fragment LDS.128 (same mapping as R5/R6):
    // tg=0 -> k0-3, tg=1 -> k8-11, tg=2 -> k4-7, tg=3 -> k12-15
    const int koff = 8 * (tg & 1) + 4 * (tg >> 1);

    // cp.async source pointers: rows g+8q of this warp's m32 tile, 16B unit u
    const float* ps[4];
    #pragma unroll
    for (int q = 0; q < 4; q++) {
        int node = tile * NPB + wid * 32 + q * 8 + g;
        if (node > n - 1) node = n - 1;
        ps[q] = x + (size_t)node * NFEAT + u * 4;
    }
    // cp.async dst base: stage-relative; row stride 64B (conflict-free both ways)
    const u32 xw = sb + OFF_X + (u32)wid * 2048 + (u32)g * 64 + (u32)u * 16;
    // fragment LDS base
    const u32 xr = sb + OFF_X + (u32)wid * 2048 + (u32)g * 64 + (u32)koff * 4;

    // ---- preamble: issue chunks 0,1,2 into stages 0,1,2 ----
    #pragma unroll
    for (int c = 0; c < 3; c++) {
        #pragma unroll
        for (int q = 0; q < 4; q++)
            cpasync16(xw + c * XSTAGE + q * 512, ps[q] + c * 16);
        cp_commit();
    }

    // ---- stage W into padded smem ----
    {
        const uint4* sH = (const uint4*)g_Wh;
        #pragma unroll
        for (int it = 0; it < 8; it++) {
            int e = tid + 256 * it;
            int row = e >> 5, c16 = e & 31;
            *(uint4*)(sm + OFF_WH + row * W_STRIDE + c16 * 16) = sH[e];
        }
    }
    // ---- stage fc head + biases ----
    u32* FCq = (u32*)(sm + OFF_FC);
    float* FCf = (float*)(sm + OFF_FC);
    FCq[FCQ + tid] = g_fc1q[tid];
    FCq[FCQ + 256 + tid] = g_fc1q[256 + tid];
    if (tid < 32) {
        FCf[FW2 + tid] = fc2w[tid];
        FCf[FB1 + tid] = fc1b[tid];
        FCf[FBZ + tid] = bz[tid];
        FCf[FBH + tid] = bh[tid];
    }
    if (tid == 0) FCf[FB2] = fc2b[0];

    // ldmatrix address for B (n16 x k16, x4), validated R3-R6
    const int rowB = (lane & 7) + ((lane >> 4) & 1) * 8;
    const u32 boff = (u32)rowB * W_STRIDE + (u32)((lane >> 3) & 1) * 16;

    float acc[2][8][4];
    #pragma unroll
    for (int mi = 0; mi < 2; mi++)
        #pragma unroll
        for (int nt = 0; nt < 8; nt++)
            #pragma unroll
            for (int r = 0; r < 4; r++) acc[mi][nt][r] = 0.f;

    __syncthreads();   // W/FC staged; the only CTA barrier

    int st = 0;        // ring stage of current chunk
    #pragma unroll 2
    for (int c = 0; c < 16; c++) {
        cp_wait2();            // groups 0..c complete (2 newest may be in flight)
        __syncwarp();          // other lanes' async stores visible

        // fragment loads from smem stage (LDS.128, conflict-free)
        float4 v[4];
        #pragma unroll
        for (int r4 = 0; r4 < 4; r4++)
            v[r4] = *(const float4*)(sm + (xr - sb) + st * XSTAGE + r4 * 512);

        // redistribute via xor-1 shuffle, convert to fp16 A fragments
        u32 AKL[4], AKH[4];
        #pragma unroll
        for (int r4 = 0; r4 < 4; r4++) {
            float4 f = v[r4];
            float s1 = ev ? f.z : f.x;
            float s2 = ev ? f.w : f.y;
            float r1 = __shfl_xor_sync(0xffffffffu, s1, 1);
            float r2 = __shfl_xor_sync(0xffffffffu, s2, 1);
            AKL[r4] = packh(ev ? f.x : r1, ev ? f.y : r2);
            AKH[r4] = packh(ev ? r1 : f.z, ev ? r2 : f.w);
        }
        u32 A0[4] = {AKL[0], AKL[1], AKH[0], AKH[1]};   // rows g, g+8
        u32 A1[4] = {AKL[2], AKL[3], AKH[2], AKH[3]};   // rows g+16, g+24

        // stage st consumed by all lanes -> refill it with chunk c+3
        __syncwarp();
        if (c + 3 < 16) {
            #pragma unroll
            for (int q = 0; q < 4; q++)
                cpasync16(xw + st * XSTAGE + q * 512, ps[q] + (c + 3) * 16);
        }
        cp_commit();           // (possibly empty) keeps group counting uniform

        // B fragments + 16 HMMAs
        const u32 kb = (u32)c * 32;
        #pragma unroll
        for (int nq = 0; nq < 4; nq++) {
            u32 b0, b1, b2, b3;
            ldsm4(sb + OFF_WH + boff + nq * 16 * W_STRIDE + kb, b0, b1, b2, b3);
            mma16816(acc[0][2 * nq],     A0, b0, b1);
            mma16816(acc[0][2 * nq + 1], A0, b2, b3);
            mma16816(acc[1][2 * nq],     A1, b0, b1);
            mma16816(acc[1][2 * nq + 1], A1, b2, b3);
        }

        st = (st == 2) ? 0 : st + 1;
    }

    // ======================= register-resident epilogue (R6, proven) =======================
    u32 Afc[2][2][4];
    #pragma unroll
    for (int mi = 0; mi < 2; mi++)
        #pragma unroll
        for (int c = 0; c < 2; c++)
            #pragma unroll
            for (int half = 0; half < 2; half++) {
                int ntz = 2 * c + half;
                float2 bzv = *(float2*)(FCf + FBZ + 8 * ntz + 2 * tg);
                float2 bhv = *(float2*)(FCf + FBH + 8 * ntz + 2 * tg);
                float h0 = (1.f - sigf(acc[mi][ntz][0] + bzv.x)) * tanhg(acc[mi][ntz + 4][0] + bhv.x);
                float h1 = (1.f - sigf(acc[mi][ntz][1] + bzv.y)) * tanhg(acc[mi][ntz + 4][1] + bhv.y);
                float h2 = (1.f - sigf(acc[mi][ntz][2] + bzv.x)) * tanhg(acc[mi][ntz + 4][2] + bhv.x);
                float h3 = (1.f - sigf(acc[mi][ntz][3] + bzv.y)) * tanhg(acc[mi][ntz + 4][3] + bhv.y);
                Afc[mi][c][half * 2 + 0] = packh(h0, h1);
                Afc[mi][c][half * 2 + 1] = packh(h2, h3);
            }

    float a2[2][4][4];
    #pragma unroll
    for (int q = 0; q < 4; q++) {
        float2 b1v = *(float2*)(FCf + FB1 + 8 * q + 2 * tg);
        #pragma unroll
        for (int mi = 0; mi < 2; mi++) {
            a2[mi][q][0] = b1v.x; a2[mi][q][1] = b1v.y;
            a2[mi][q][2] = b1v.x; a2[mi][q][3] = b1v.y;
        }
    }
    #pragma unroll
    for (int c = 0; c < 2; c++)
        #pragma unroll
        for (int q = 0; q < 4; q++) {
            u32 bf0 = FCq[FCQ + (tg + 8 * c) * 32 + g + 8 * q];
            u32 bf1 = FCq[FCQ + (tg + 4 + 8 * c) * 32 + g + 8 * q];
            mma16816(a2[0][q], Afc[0][c], bf0, bf1);
            mma16816(a2[1][q], Afc[1][c], bf0, bf1);
        }

    const float b2 = FCf[FB2];
    #pragma unroll
    for (int mi = 0; mi < 2; mi++) {
        float og = 0.f, og8 = 0.f;
        #pragma unroll
        for (int q = 0; q < 4; q++) {
            float2 w2 = *(float2*)(FCf + FW2 + 8 * q + 2 * tg);
            og  = fmaf(fmaxf(a2[mi][q][0], 0.f), w2.x, og);
            og  = fmaf(fmaxf(a2[mi][q][1], 0.f), w2.y, og);
            og8 = fmaf(fmaxf(a2[mi][q][2], 0.f), w2.x, og8);
            og8 = fmaf(fmaxf(a2[mi][q][3], 0.f), w2.y, og8);
        }
        og  += __shfl_xor_sync(0xffffffffu, og, 1);
        og  += __shfl_xor_sync(0xffffffffu, og, 2);
        og8 += __shfl_xor_sync(0xffffffffu, og8, 1);
        og8 += __shfl_xor_sync(0xffffffffu, og8, 2);
        if (tg == 0) {
            int node = tile * NPB + wid * 32 + mi * 16 + g;
            if (node < n)     out[node]     = sigf(og + b2);
            if (node + 8 < n) out[node + 8] = sigf(og8 + b2);
        }
    }
}

// ---------------------------------------------------------------------------
// Launch. Inputs: x, edge_index(dead), w_z, b_z, w_r(dead), b_r(dead),
// w_h, b_h, fc1_w, fc1_b, fc2_w, fc2_b. Output: [N,1] float.
// ---------------------------------------------------------------------------
extern "C" void kernel_launch(void* const* d_in, const int* in_sizes, int n_in,
                              void* d_out, int out_size) {
    const float* x    = (const float*)d_in[0];
    const float* wz   = (const float*)d_in[2];
    const float* bz   = (const float*)d_in[3];
    const float* wh   = (const float*)d_in[6];
    const float* bh   = (const float*)d_in[7];
    const float* fc1w = (const float*)d_in[8];
    const float* fc1b = (const float*)d_in[9];
    const float* fc2w = (const float*)d_in[10];
    const float* fc2b = (const float*)d_in[11];
    float* out = (float*)d_out;

    const int n = out_size;
    const int ntiles = (n + NPB - 1) / NPB;

    prep_kernel<<<64, 256>>>(wz, wh, fc1w);

    cudaFuncSetAttribute(fused_kernel, cudaFuncAttributeMaxDynamicSharedMemorySize, SMEM_BYTES);
    fused_kernel<<<ntiles, NTHR, SMEM_BYTES>>>(x, bz, bh, fc1b, fc2w, fc2b, out, n);
}